// round 4
// baseline (speedup 1.0000x reference)
#include <cuda_runtime.h>
#include <math.h>

// InstanceAwarePointMatching:
//   score = exp(msm) [P,R,S]
//   row top-3 along s -> scatter; col top-3 along r -> scatter
//   score_map = 0.5*(ref+src) ; corr_map = (ref_hit & mask) | (src_hit & mask)
//
// Masks (bool in the reference) arrive as 4-byte elements (harness converts
// bools to float32/int32): read as uint32 and test != 0. Reading them as bytes
// produced the R3 signature rel_err = sqrt(15/16).
//
// Top-k exactness: keep top-4 on RAW scores ordered by (value desc, idx asc),
// then re-rank the 4 finalists by (expf desc, idx asc) and scatter the top 3 —
// reproduces jax.lax.top_k over exp() including float32 exp-rounding ties.

struct T4 { float v0, v1, v2, v3; int i0, i1, i2, i3; };

__device__ __forceinline__ bool better(float v, int i, float w, int j) {
    return (v > w) || (v == w && (unsigned)i < (unsigned)j);
}

__device__ __forceinline__ void t4_init(T4& t) {
    t.v0 = t.v1 = t.v2 = t.v3 = -INFINITY;
    t.i0 = t.i1 = t.i2 = t.i3 = 0x7FFFFFFF;
}

__device__ __forceinline__ void t4_insert(T4& t, float v, int i) {
    if (better(v, i, t.v3, t.i3)) {
        if (better(v, i, t.v2, t.i2)) {
            t.v3 = t.v2; t.i3 = t.i2;
            if (better(v, i, t.v1, t.i1)) {
                t.v2 = t.v1; t.i2 = t.i1;
                if (better(v, i, t.v0, t.i0)) {
                    t.v1 = t.v0; t.i1 = t.i0;
                    t.v0 = v; t.i0 = i;
                } else { t.v1 = v; t.i1 = i; }
            } else { t.v2 = v; t.i2 = i; }
        } else { t.v3 = v; t.i3 = i; }
    }
}

// Re-rank the 4 raw-score finalists by (expf desc, idx asc); emit top-3.
__device__ __forceinline__ void finalize3(const T4& t, float* ev, int* ei) {
    float e[4] = { expf(t.v0), expf(t.v1), expf(t.v2), expf(t.v3) };
    int   x[4] = { t.i0, t.i1, t.i2, t.i3 };
    #pragma unroll
    for (int a = 1; a < 4; a++) {
        #pragma unroll
        for (int b = a; b > 0; b--) {
            if (better(e[b], x[b], e[b-1], x[b-1])) {
                float tv = e[b]; e[b] = e[b-1]; e[b-1] = tv;
                int   ti = x[b]; x[b] = x[b-1]; x[b-1] = ti;
            }
        }
    }
    #pragma unroll
    for (int k = 0; k < 3; k++) { ev[k] = e[k]; ei[k] = x[k]; }
}

// ---------------------------------------------------------------------------
// Row top-k: ONE THREAD per (p, r). float4 sweep along s with max4 prefilter.
// Per-thread line reuse makes the (lane-uncoalesced) loads L1-friendly.
// ---------------------------------------------------------------------------
template <typename CorrT>
__global__ void row_topk_scatter(const float* __restrict__ msm,
                                 const unsigned int* __restrict__ refm,
                                 const unsigned int* __restrict__ srcm,
                                 float* __restrict__ score_out,
                                 CorrT* __restrict__ corr_out,
                                 int P, int R, int S)
{
    const int row = (int)(blockIdx.x * (size_t)blockDim.x + threadIdx.x);
    if (row >= P * R) return;
    const int p = row / R;

    const float4* __restrict__ rowp =
        (const float4*)(msm + (size_t)row * S);
    const int nj = S >> 2;

    T4 t; t4_init(t);
    #pragma unroll 4
    for (int j = 0; j < nj; j++) {
        const float4 v = __ldg(rowp + j);
        const float mx = fmaxf(fmaxf(v.x, v.y), fmaxf(v.z, v.w));
        if (mx >= t.v3) {                    // >= keeps exact tie behavior
            const int s0 = j << 2;
            t4_insert(t, v.x, s0);
            t4_insert(t, v.y, s0 + 1);
            t4_insert(t, v.z, s0 + 2);
            t4_insert(t, v.w, s0 + 3);
        }
    }

    float ev[3]; int ei[3];
    finalize3(t, ev, ei);
    const bool rm = refm[row] != 0u;
    #pragma unroll
    for (int k = 0; k < 3; k++) {
        const int s = ei[k];
        if ((unsigned)s < (unsigned)S) {
            atomicAdd(&score_out[(size_t)row * S + s], 0.5f * ev[k]);
            if (rm && srcm[(size_t)p * S + s] != 0u) {
                corr_out[(size_t)row * S + s] = (CorrT)1;
            }
        }
    }
}

// ---------------------------------------------------------------------------
// Col top-k: ONE THREAD per (p, 4 columns). float4 across s (coalesced),
// 4 register states, prefilter against running min of the four v3s.
// ---------------------------------------------------------------------------
template <typename CorrT>
__global__ void col_topk_scatter(const float* __restrict__ msm,
                                 const unsigned int* __restrict__ refm,
                                 const unsigned int* __restrict__ srcm,
                                 float* __restrict__ score_out,
                                 CorrT* __restrict__ corr_out,
                                 int P, int R, int S)
{
    const int sq = S >> 2;
    const int idx = (int)(blockIdx.x * (size_t)blockDim.x + threadIdx.x);
    if (idx >= P * sq) return;
    const int p  = idx / sq;
    const int s0 = (idx - p * sq) << 2;

    const float* __restrict__ base = msm + (size_t)p * R * S + s0;

    T4 st[4];
    #pragma unroll
    for (int k = 0; k < 4; k++) t4_init(st[k]);
    float mmin = -INFINITY;

    #pragma unroll 4
    for (int r = 0; r < R; r++) {
        const float4 v = __ldg((const float4*)(base + (size_t)r * S));
        const float mx = fmaxf(fmaxf(v.x, v.y), fmaxf(v.z, v.w));
        if (mx >= mmin) {
            t4_insert(st[0], v.x, r);
            t4_insert(st[1], v.y, r);
            t4_insert(st[2], v.z, r);
            t4_insert(st[3], v.w, r);
            mmin = fminf(fminf(st[0].v3, st[1].v3),
                         fminf(st[2].v3, st[3].v3));
        }
    }

    #pragma unroll
    for (int k = 0; k < 4; k++) {
        float ev[3]; int ei[3];
        finalize3(st[k], ev, ei);
        const int s = s0 + k;
        const bool sm = srcm[(size_t)p * S + s] != 0u;
        #pragma unroll
        for (int q = 0; q < 3; q++) {
            const int r = ei[q];
            if ((unsigned)r < (unsigned)R) {
                atomicAdd(&score_out[((size_t)p * R + r) * S + s], 0.5f * ev[q]);
                if (sm && refm[(size_t)p * R + r] != 0u) {
                    corr_out[((size_t)p * R + r) * S + s] = (CorrT)1;
                }
            }
        }
    }
}

extern "C" void kernel_launch(void* const* d_in, const int* in_sizes, int n_in,
                              void* d_out, int out_size)
{
    const float*        msm  = (const float*)d_in[0];
    // d_in[1] = node_corr_scores (unused: conditional=False)
    const unsigned int* refm = (const unsigned int*)d_in[2];   // bool -> 4-byte
    const unsigned int* srcm = (const unsigned int*)d_in[3];   // bool -> 4-byte

    const int P = in_sizes[1];          // node_corr_scores: [P]
    const int R = in_sizes[2] / P;      // ref_knn_masks: [P, R]
    const int S = in_sizes[3] / P;      // src_knn_masks: [P, S]
    const size_t N = (size_t)P * R * S;

    float* score_out = (float*)d_out;

    const int row_total = P * R;
    const int row_threads = 256;
    const int row_blocks = (row_total + row_threads - 1) / row_threads;
    const int col_total = P * (S >> 2);
    const int col_threads = 256;
    const int col_blocks = (col_total + col_threads - 1) / col_threads;

    if ((size_t)out_size == 2 * N) {
        // [score_map (f32) | corr_map (f32)]
        cudaMemsetAsync(d_out, 0, 2 * N * sizeof(float), 0);
        float* corr_out = score_out + N;
        row_topk_scatter<float><<<row_blocks, row_threads>>>(
            msm, refm, srcm, score_out, corr_out, P, R, S);
        col_topk_scatter<float><<<col_blocks, col_threads>>>(
            msm, refm, srcm, score_out, corr_out, P, R, S);
    } else {
        // [score_map (f32) | corr_map (u8)]
        cudaMemsetAsync(d_out, 0, N * sizeof(float) + N, 0);
        unsigned char* corr_out = (unsigned char*)d_out + N * sizeof(float);
        row_topk_scatter<unsigned char><<<row_blocks, row_threads>>>(
            msm, refm, srcm, score_out, corr_out, P, R, S);
        col_topk_scatter<unsigned char><<<col_blocks, col_threads>>>(
            msm, refm, srcm, score_out, corr_out, P, R, S);
    }
}